// round 6
// baseline (speedup 1.0000x reference)
#include <cuda_runtime.h>
#include <cstdint>

#define NN 50000
#define HH 128
#define CC 16
#define RR 8
#define BB 4
#define EE 800000

// ---------------- scratch (device globals: allowed; no allocations) ----------------
__device__ float g_x0[(size_t)NN * HH];        // layer0 output / layer1 input (25.6 MB)
__device__ float g_x1[(size_t)NN * HH];        // layer1 output / layer2 input (25.6 MB)
__device__ float g_w1[RR * HH * HH];           // composed layer1 weights (512 KB)
__device__ float g_w2[RR * HH * CC];           // composed layer2 weights (64 KB)
__device__ float g_t1[(size_t)RR * NN * HH];   // layer1 per-relation transforms (204.8 MB)
__device__ float g_t2[(size_t)RR * NN * CC];   // layer2 per-relation transforms (25.6 MB)

// ---------------- helpers ----------------
__device__ __forceinline__ void redAdd4(float* p, float4 v) {
    asm volatile("red.global.add.v4.f32 [%0], {%1, %2, %3, %4};"
                 :: "l"(__cvta_generic_to_global(p)),
                    "f"(v.x), "f"(v.y), "f"(v.z), "f"(v.w)
                 : "memory");
}

// ---------------- compose basis weights: out[r,:,:] = sum_b wc[r,b]*bases[b,:,:] ----------------
__global__ void combine_w(const float* __restrict__ wc, const float* __restrict__ bases,
                          float* __restrict__ out, int slice, int total) {
    int i = blockIdx.x * blockDim.x + threadIdx.x;
    if (i >= total) return;
    int rel = i / slice;
    int rem = i - rel * slice;
    float a = 0.f;
#pragma unroll
    for (int b = 0; b < BB; b++)
        a = fmaf(__ldg(&wc[rel * BB + b]), __ldg(&bases[(size_t)b * slice + rem]), a);
    out[i] = a;
}

// ---------------- layer 0 init: x0[n,f] = loop0[h[n],f] + bias0[f] ----------------
__global__ void init0_k(const int* __restrict__ h, const float* __restrict__ loop0,
                        const float* __restrict__ bias0, float* __restrict__ out) {
    int i = blockIdx.x * 256 + threadIdx.x;
    if (i >= NN * HH) return;
    int n = i >> 7;
    int f = i & 127;
    int id = __ldg(&h[n]);
    out[i] = __ldg(&loop0[(size_t)id * HH + f]) + __ldg(&bias0[f]);
}

// ---------------- layer 0 scatter: one warp per edge ----------------
__global__ void __launch_bounds__(256) scatter0_k(
    const int* __restrict__ src, const int* __restrict__ dst, const int* __restrict__ h,
    const int* __restrict__ rel, const float* __restrict__ norm,
    const float* __restrict__ bases0, const float* __restrict__ wcomp0,
    float* __restrict__ out) {
    int e = (blockIdx.x * 256 + threadIdx.x) >> 5;
    if (e >= EE) return;
    int lane = threadIdx.x & 31;
    int s  = __ldg(&src[e]);
    int d  = __ldg(&dst[e]);
    int rr = __ldg(&rel[e]);
    float nm = __ldg(&norm[e]);
    int sid = __ldg(&h[s]);
    float c0 = nm * __ldg(&wcomp0[rr * 4 + 0]);
    float c1 = nm * __ldg(&wcomp0[rr * 4 + 1]);
    float c2 = nm * __ldg(&wcomp0[rr * 4 + 2]);
    float c3 = nm * __ldg(&wcomp0[rr * 4 + 3]);
    const float4* bp = (const float4*)bases0;
    const long BS = (long)NN * 32;                  // per-basis slice in float4 units
    long base = (long)sid * 32 + lane;
    float4 v0 = __ldg(bp + base);
    float4 v1 = __ldg(bp + base + BS);
    float4 v2 = __ldg(bp + base + 2 * BS);
    float4 v3 = __ldg(bp + base + 3 * BS);
    float4 m;
    m.x = c0 * v0.x + c1 * v1.x + c2 * v2.x + c3 * v3.x;
    m.y = c0 * v0.y + c1 * v1.y + c2 * v2.y + c3 * v3.y;
    m.z = c0 * v0.z + c1 * v1.z + c2 * v2.z + c3 * v3.z;
    m.w = c0 * v0.w + c1 * v1.w + c2 * v2.w + c3 * v3.w;
    redAdd4(out + (long)d * HH + lane * 4, m);
}

// ---------------- relu ----------------
__global__ void relu_k(float* __restrict__ x, int n) {
    int i = blockIdx.x * 256 + threadIdx.x;
    if (i < n) x[i] = fmaxf(x[i], 0.f);
}

// ---------------- dense transform, F=128: Out[y] = X @ W[y] (+bias) ----------------
__global__ void __launch_bounds__(128) transform128(
    const float* __restrict__ X, const float* __restrict__ Wbase, long wstride,
    float* __restrict__ Outbase, long ostride, const float* __restrict__ bias, int nrows) {
    __shared__ float xs[64][128];
    const float* W = Wbase + (long)blockIdx.y * wstride;
    float* Out = Outbase + (long)blockIdx.y * ostride;
    const int t = threadIdx.x;
    const int row0 = blockIdx.x * 64;
#pragma unroll 4
    for (int i = 0; i < 64; i++) {
        int rr = row0 + i;
        xs[i][t] = (rr < nrows) ? __ldg(&X[(long)rr * 128 + t]) : 0.f;
    }
    __syncthreads();
    const float bv = bias ? __ldg(&bias[t]) : 0.f;
    for (int i0 = 0; i0 < 64; i0 += 4) {
        float a0 = 0.f, a1 = 0.f, a2 = 0.f, a3 = 0.f;
#pragma unroll 8
        for (int d = 0; d < 128; d++) {
            float w = __ldg(&W[d * 128 + t]);
            a0 = fmaf(xs[i0 + 0][d], w, a0);
            a1 = fmaf(xs[i0 + 1][d], w, a1);
            a2 = fmaf(xs[i0 + 2][d], w, a2);
            a3 = fmaf(xs[i0 + 3][d], w, a3);
        }
        int rr = row0 + i0;
        if (rr + 3 < nrows) {
            Out[(long)(rr + 0) * 128 + t] = a0 + bv;
            Out[(long)(rr + 1) * 128 + t] = a1 + bv;
            Out[(long)(rr + 2) * 128 + t] = a2 + bv;
            Out[(long)(rr + 3) * 128 + t] = a3 + bv;
        } else {
            if (rr + 0 < nrows) Out[(long)(rr + 0) * 128 + t] = a0 + bv;
            if (rr + 1 < nrows) Out[(long)(rr + 1) * 128 + t] = a1 + bv;
            if (rr + 2 < nrows) Out[(long)(rr + 2) * 128 + t] = a2 + bv;
            if (rr + 3 < nrows) Out[(long)(rr + 3) * 128 + t] = a3 + bv;
        }
    }
}

// ---------------- layer 1 scatter: one warp per edge, gather from trans ----------------
__global__ void __launch_bounds__(256) scatter1_k(
    const int* __restrict__ src, const int* __restrict__ dst, const int* __restrict__ rel,
    const float* __restrict__ norm, const float* __restrict__ trans, float* __restrict__ out) {
    int e = (blockIdx.x * 256 + threadIdx.x) >> 5;
    if (e >= EE) return;
    int lane = threadIdx.x & 31;
    int s  = __ldg(&src[e]);
    int d  = __ldg(&dst[e]);
    int rr = __ldg(&rel[e]);
    float nm = __ldg(&norm[e]);
    const float4* tp = (const float4*)trans;
    float4 v = __ldg(tp + ((long)rr * NN + s) * 32 + lane);
    float4 m = {v.x * nm, v.y * nm, v.z * nm, v.w * nm};
    redAdd4(out + (long)d * HH + lane * 4, m);
}

// ---------------- dense transform, F=16 ----------------
__global__ void __launch_bounds__(128) transform16(
    const float* __restrict__ X, const float* __restrict__ Wbase, long wstride,
    float* __restrict__ Outbase, long ostride, const float* __restrict__ bias, int nrows) {
    __shared__ float ws[128 * 16];
    __shared__ float xs[64][129];   // pad: 2 rows per warp -> distinct banks
    const float* W = Wbase + (long)blockIdx.y * wstride;
    float* Out = Outbase + (long)blockIdx.y * ostride;
    const int t = threadIdx.x;
    const int col = t & 15, rg = t >> 4;
    const int row0 = blockIdx.x * 64;
    for (int i = t; i < 128 * 16; i += 128) ws[i] = __ldg(&W[i]);
#pragma unroll 4
    for (int i = 0; i < 64; i++) {
        int rr = row0 + i;
        xs[i][t] = (rr < nrows) ? __ldg(&X[(long)rr * 128 + t]) : 0.f;
    }
    __syncthreads();
    const float bv = bias ? __ldg(&bias[col]) : 0.f;
    for (int p = 0; p < 8; p++) {
        int rl = p * 8 + rg;
        float a = 0.f;
#pragma unroll 16
        for (int d = 0; d < 128; d++) a = fmaf(xs[rl][d], ws[d * 16 + col], a);
        int rr = row0 + rl;
        if (rr < nrows) Out[(long)rr * 16 + col] = a + bv;
    }
}

// ---------------- layer 2 scatter: 4 lanes per edge ----------------
__global__ void __launch_bounds__(256) scatter2_k(
    const int* __restrict__ src, const int* __restrict__ dst, const int* __restrict__ rel,
    const float* __restrict__ norm, const float* __restrict__ trans, float* __restrict__ out) {
    int tid = blockIdx.x * 256 + threadIdx.x;
    int e = tid >> 2;
    if (e >= EE) return;
    int q = tid & 3;
    int s  = __ldg(&src[e]);
    int d  = __ldg(&dst[e]);
    int rr = __ldg(&rel[e]);
    float nm = __ldg(&norm[e]);
    const float4* tp = (const float4*)trans;
    float4 v = __ldg(tp + ((long)rr * NN + s) * 4 + q);
    float4 m = {v.x * nm, v.y * nm, v.z * nm, v.w * nm};
    redAdd4(out + (long)d * CC + q * 4, m);
}

// ---------------- launch ----------------
extern "C" void kernel_launch(void* const* d_in, const int* in_sizes, int n_in,
                              void* d_out, int out_size) {
    const int*   src    = (const int*)d_in[0];
    const int*   dst    = (const int*)d_in[1];
    const int*   h      = (const int*)d_in[2];
    const int*   rtab   = (const int*)d_in[3];
    const float* norm   = (const float*)d_in[4];
    const float* bases0 = (const float*)d_in[5];
    const float* wcomp0 = (const float*)d_in[6];
    const float* loop0  = (const float*)d_in[7];
    const float* bias0  = (const float*)d_in[8];
    const float* bases1 = (const float*)d_in[9];
    const float* wcomp1 = (const float*)d_in[10];
    const float* loop1  = (const float*)d_in[11];
    const float* bias1  = (const float*)d_in[12];
    const float* bases2 = (const float*)d_in[13];
    const float* wcomp2 = (const float*)d_in[14];
    const float* loop2  = (const float*)d_in[15];
    const float* bias2  = (const float*)d_in[16];
    float* out = (float*)d_out;

    float *p_x0, *p_x1, *p_w1, *p_w2, *p_t1, *p_t2;
    cudaGetSymbolAddress((void**)&p_x0, g_x0);
    cudaGetSymbolAddress((void**)&p_x1, g_x1);
    cudaGetSymbolAddress((void**)&p_w1, g_w1);
    cudaGetSymbolAddress((void**)&p_w2, g_w2);
    cudaGetSymbolAddress((void**)&p_t1, g_t1);
    cudaGetSymbolAddress((void**)&p_t2, g_t2);

    const int nh_blocks  = (NN * HH + 255) / 256;          // 25000
    const int edge_warp  = (EE * 32 + 255) / 256;          // 100000 (warp/edge)
    const int row_tiles  = (NN + 63) / 64;                 // 782

    // compose per-relation weights
    combine_w<<<(RR * HH * HH + 255) / 256, 256>>>(wcomp1, bases1, p_w1, HH * HH, RR * HH * HH);
    combine_w<<<(RR * HH * CC + 255) / 256, 256>>>(wcomp2, bases2, p_w2, HH * CC, RR * HH * CC);

    // ---- layer 0 ----
    init0_k<<<nh_blocks, 256>>>(h, loop0, bias0, p_x0);
    scatter0_k<<<edge_warp, 256>>>(src, dst, h, rtab, norm, bases0, wcomp0, p_x0);
    relu_k<<<nh_blocks, 256>>>(p_x0, NN * HH);

    // ---- layer 1 ----
    transform128<<<dim3(row_tiles, RR), 128>>>(p_x0, p_w1, (long)HH * HH, p_t1, (long)NN * HH, nullptr, NN);
    transform128<<<dim3(row_tiles, 1), 128>>>(p_x0, loop1, 0, p_x1, 0, bias1, NN);
    scatter1_k<<<edge_warp, 256>>>(src, dst, rtab, norm, p_t1, p_x1);
    relu_k<<<nh_blocks, 256>>>(p_x1, NN * HH);

    // ---- layer 2 ----
    transform16<<<dim3(row_tiles, RR), 128>>>(p_x1, p_w2, (long)HH * CC, p_t2, (long)NN * CC, nullptr, NN);
    transform16<<<dim3(row_tiles, 1), 128>>>(p_x1, loop2, 0, out, 0, bias2, NN);
    scatter2_k<<<(EE * 4 + 255) / 256, 256>>>(src, dst, rtab, norm, p_t2, out);
}

// round 8
// speedup vs baseline: 1.9053x; 1.9053x over previous
#include <cuda_runtime.h>
#include <cuda_bf16.h>
#include <cstdint>

#define NN 50000
#define HH 128
#define CC 16
#define RR 8
#define BB 4
#define EE 800000

// ---------------- scratch (device globals; no allocations) ----------------
__device__ float g_x0[(size_t)NN * HH];              // layer0 out (pre-relu)
__device__ float g_x1[(size_t)NN * HH];              // layer1 out (pre-relu)
__device__ float g_y1[(size_t)4 * NN * HH];          // layer1 basis products Y_b = relu(x0)@B1_b
__device__ float g_z2[(size_t)4 * NN * CC];          // layer2 basis products Z_b = relu(x1)@B2_b
__device__ __nv_bfloat16 g_w1thi[5 * 128 * 128];     // transposed bf16 hi: slices 0..3 = bases1^T, 4 = loop1^T
__device__ __nv_bfloat16 g_w1tlo[5 * 128 * 128];     // residual lo

// ---------------- helpers ----------------
__device__ __forceinline__ void redAdd4(float* p, float4 v) {
    asm volatile("red.global.add.v4.f32 [%0], {%1, %2, %3, %4};"
                 :: "l"(__cvta_generic_to_global(p)), "f"(v.x), "f"(v.y), "f"(v.z), "f"(v.w)
                 : "memory");
}
__device__ __forceinline__ uint32_t pack_bf16(float a, float b) {
    __nv_bfloat162 t = __floats2bfloat162_rn(a, b);
    return *(uint32_t*)&t;
}
#define MMA16816(c, a0, a1, a2, a3, b0, b1)                                   \
    asm volatile("mma.sync.aligned.m16n8k16.row.col.f32.bf16.bf16.f32 "       \
                 "{%0,%1,%2,%3}, {%4,%5,%6,%7}, {%8,%9}, {%0,%1,%2,%3};"      \
                 : "+f"((c)[0]), "+f"((c)[1]), "+f"((c)[2]), "+f"((c)[3])     \
                 : "r"(a0), "r"(a1), "r"(a2), "r"(a3), "r"(b0), "r"(b1))

// smem layout for mma_t128 (bf16 row stride 136 = 128 + 8 pad -> conflict-free frag LDS)
#define LSTRIDE 136
#define AH_OFF 0
#define AL_OFF 34816
#define WH_OFF 69632
#define WL_OFF 104448
#define SMEM_MMA 139264

// ---------------- prep: transpose + bf16 hi/lo split of layer-1 weights ----------------
// out[s][f][d], s: 0..3 = bases1[s], 4 = loop1.  src layout [d][f] (f contiguous).
__global__ void prep_w1t(const float* __restrict__ bases1, const float* __restrict__ loop1,
                         __nv_bfloat16* __restrict__ whi, __nv_bfloat16* __restrict__ wlo) {
    int i = blockIdx.x * 256 + threadIdx.x;
    if (i >= 5 * 16384) return;
    int s = i >> 14;
    int f = (i >> 7) & 127;
    int d = i & 127;
    float v = (s < 4) ? __ldg(&bases1[s * 16384 + d * 128 + f]) : __ldg(&loop1[d * 128 + f]);
    __nv_bfloat16 hi = __float2bfloat16(v);
    __nv_bfloat16 lo = __float2bfloat16(v - __bfloat162float(hi));
    whi[i] = hi;
    wlo[i] = lo;
}

// ---------------- layer 0 init: x0 = loop0[h] + bias0 ----------------
__global__ void init0_k(const int* __restrict__ h, const float* __restrict__ loop0,
                        const float* __restrict__ bias0, float* __restrict__ out) {
    int i = blockIdx.x * 256 + threadIdx.x;
    if (i >= NN * HH) return;
    int n = i >> 7;
    int f = i & 127;
    int id = __ldg(&h[n]);
    out[i] = __ldg(&loop0[(size_t)id * HH + f]) + __ldg(&bias0[f]);
}

// ---------------- layer 0 scatter: one warp per edge, basis-gather ----------------
__global__ void __launch_bounds__(256) scatter0_k(
    const int* __restrict__ src, const int* __restrict__ dst, const int* __restrict__ h,
    const int* __restrict__ rel, const float* __restrict__ norm,
    const float* __restrict__ bases0, const float* __restrict__ wcomp0,
    float* __restrict__ out) {
    int e = (blockIdx.x * 256 + threadIdx.x) >> 5;
    if (e >= EE) return;
    int lane = threadIdx.x & 31;
    int s = __ldg(&src[e]);
    int d = __ldg(&dst[e]);
    int rr = __ldg(&rel[e]);
    float nm = __ldg(&norm[e]);
    int sid = __ldg(&h[s]);
    float c0 = nm * __ldg(&wcomp0[rr * 4 + 0]);
    float c1 = nm * __ldg(&wcomp0[rr * 4 + 1]);
    float c2 = nm * __ldg(&wcomp0[rr * 4 + 2]);
    float c3 = nm * __ldg(&wcomp0[rr * 4 + 3]);
    const float4* bp = (const float4*)bases0;
    const long BS = (long)NN * 32;
    long base = (long)sid * 32 + lane;
    float4 v0 = __ldg(bp + base);
    float4 v1 = __ldg(bp + base + BS);
    float4 v2 = __ldg(bp + base + 2 * BS);
    float4 v3 = __ldg(bp + base + 3 * BS);
    float4 m;
    m.x = c0 * v0.x + c1 * v1.x + c2 * v2.x + c3 * v3.x;
    m.y = c0 * v0.y + c1 * v1.y + c2 * v2.y + c3 * v3.y;
    m.z = c0 * v0.z + c1 * v1.z + c2 * v2.z + c3 * v3.z;
    m.w = c0 * v0.w + c1 * v1.w + c2 * v2.w + c3 * v3.w;
    redAdd4(out + (long)d * HH + lane * 4, m);
}

// ---------------- HMMA transform: out[slice] = relu(x0) @ Wt[slice]^T, bf16 hi/lo split ----------------
// grid = (391, 5): slice<4 -> Y_b; slice==4 -> x1 = . + bias1
__global__ void __launch_bounds__(256) mma_t128(
    const float* __restrict__ X,
    const __nv_bfloat16* __restrict__ Wth, const __nv_bfloat16* __restrict__ Wtl,
    float* __restrict__ Y, float* __restrict__ x1, const float* __restrict__ bias1) {
    extern __shared__ char sm[];
    const int tid = threadIdx.x;
    const int w = tid >> 5;
    const int lane = tid & 31;
    const int slice = blockIdx.y;
    const int row0 = blockIdx.x * 128;

    // ---- fill W hi/lo (already [f][d] with d contiguous = B col-major) ----
    {
        int r = tid >> 1, half = tid & 1;
        const uint4* gh = (const uint4*)(Wth + slice * 16384) + r * 16 + half * 8;
        const uint4* gl = (const uint4*)(Wtl + slice * 16384) + r * 16 + half * 8;
        uint4* dh = (uint4*)(sm + WH_OFF + r * (LSTRIDE * 2) + half * 128);
        uint4* dl = (uint4*)(sm + WL_OFF + r * (LSTRIDE * 2) + half * 128);
#pragma unroll
        for (int i = 0; i < 8; i++) { dh[i] = __ldg(gh + i); dl[i] = __ldg(gl + i); }
    }
    // ---- fill A: relu(x0) tile, bf16 hi/lo split ----
    {
        int r = tid >> 1, half = tid & 1;
        int rg = row0 + r;
        const float4* xr = (const float4*)X + (long)rg * 32 + half * 16;
        uint32_t* ah = (uint32_t*)(sm + AH_OFF + r * (LSTRIDE * 2) + half * 128);
        uint32_t* al = (uint32_t*)(sm + AL_OFF + r * (LSTRIDE * 2) + half * 128);
#pragma unroll
        for (int i = 0; i < 16; i++) {
            float4 q = (rg < NN) ? __ldg(xr + i) : make_float4(0.f, 0.f, 0.f, 0.f);
            q.x = fmaxf(q.x, 0.f); q.y = fmaxf(q.y, 0.f);
            q.z = fmaxf(q.z, 0.f); q.w = fmaxf(q.w, 0.f);
            float hx = __bfloat162float(__float2bfloat16(q.x));
            float hy = __bfloat162float(__float2bfloat16(q.y));
            float hz = __bfloat162float(__float2bfloat16(q.z));
            float hw = __bfloat162float(__float2bfloat16(q.w));
            ah[i * 2]     = pack_bf16(q.x, q.y);
            ah[i * 2 + 1] = pack_bf16(q.z, q.w);
            al[i * 2]     = pack_bf16(q.x - hx, q.y - hy);
            al[i * 2 + 1] = pack_bf16(q.z - hz, q.w - hw);
        }
    }
    __syncthreads();

    // ---- compute: warp w owns rows [16w,16w+16), all 16 n8-tiles ----
    float acc[16][4];
#pragma unroll
    for (int j = 0; j < 16; j++) { acc[j][0] = acc[j][1] = acc[j][2] = acc[j][3] = 0.f; }
    const int g = lane >> 2, tg = lane & 3;
    const int ra = w * 16 + g;

    for (int ks = 0; ks < 8; ks++) {
        int kb = ks * 16 + tg * 2;
        uint32_t ah0 = *(const uint32_t*)(sm + AH_OFF + ((ra)     * LSTRIDE + kb)     * 2);
        uint32_t ah1 = *(const uint32_t*)(sm + AH_OFF + ((ra + 8) * LSTRIDE + kb)     * 2);
        uint32_t ah2 = *(const uint32_t*)(sm + AH_OFF + ((ra)     * LSTRIDE + kb + 8) * 2);
        uint32_t ah3 = *(const uint32_t*)(sm + AH_OFF + ((ra + 8) * LSTRIDE + kb + 8) * 2);
        uint32_t al0 = *(const uint32_t*)(sm + AL_OFF + ((ra)     * LSTRIDE + kb)     * 2);
        uint32_t al1 = *(const uint32_t*)(sm + AL_OFF + ((ra + 8) * LSTRIDE + kb)     * 2);
        uint32_t al2 = *(const uint32_t*)(sm + AL_OFF + ((ra)     * LSTRIDE + kb + 8) * 2);
        uint32_t al3 = *(const uint32_t*)(sm + AL_OFF + ((ra + 8) * LSTRIDE + kb + 8) * 2);
#pragma unroll
        for (int j = 0; j < 16; j++) {
            int n = j * 8 + g;
            uint32_t bh0 = *(const uint32_t*)(sm + WH_OFF + (n * LSTRIDE + kb)     * 2);
            uint32_t bh1 = *(const uint32_t*)(sm + WH_OFF + (n * LSTRIDE + kb + 8) * 2);
            uint32_t bl0 = *(const uint32_t*)(sm + WL_OFF + (n * LSTRIDE + kb)     * 2);
            uint32_t bl1 = *(const uint32_t*)(sm + WL_OFF + (n * LSTRIDE + kb + 8) * 2);
            MMA16816(acc[j], ah0, ah1, ah2, ah3, bh0, bh1);
            MMA16816(acc[j], ah0, ah1, ah2, ah3, bl0, bl1);
            MMA16816(acc[j], al0, al1, al2, al3, bh0, bh1);
        }
    }

    // ---- epilogue ----
    float* O = (slice < 4) ? (Y + (long)slice * NN * HH) : x1;
    long r0 = row0 + ra;
    long r1 = r0 + 8;
#pragma unroll
    for (int j = 0; j < 16; j++) {
        int col = j * 8 + tg * 2;
        float b0 = 0.f, b1 = 0.f;
        if (slice == 4) { b0 = __ldg(&bias1[col]); b1 = __ldg(&bias1[col + 1]); }
        if (r0 < NN) {
            float2 v = { acc[j][0] + b0, acc[j][1] + b1 };
            *(float2*)(O + r0 * 128 + col) = v;
        }
        if (r1 < NN) {
            float2 v = { acc[j][2] + b0, acc[j][3] + b1 };
            *(float2*)(O + r1 * 128 + col) = v;
        }
    }
}

// ---------------- layer 1 scatter: warp/edge, gather 4 basis rows of Y ----------------
__global__ void __launch_bounds__(256) scatter1_k(
    const int* __restrict__ src, const int* __restrict__ dst, const int* __restrict__ rel,
    const float* __restrict__ norm, const float* __restrict__ wcomp1,
    const float* __restrict__ Y, float* __restrict__ out) {
    int e = (blockIdx.x * 256 + threadIdx.x) >> 5;
    if (e >= EE) return;
    int lane = threadIdx.x & 31;
    int s = __ldg(&src[e]);
    int d = __ldg(&dst[e]);
    int rr = __ldg(&rel[e]);
    float nm = __ldg(&norm[e]);
    float c0 = nm * __ldg(&wcomp1[rr * 4 + 0]);
    float c1 = nm * __ldg(&wcomp1[rr * 4 + 1]);
    float c2 = nm * __ldg(&wcomp1[rr * 4 + 2]);
    float c3 = nm * __ldg(&wcomp1[rr * 4 + 3]);
    const float4* yp = (const float4*)Y;
    const long SS = (long)NN * 32;
    long base = (long)s * 32 + lane;
    float4 v0 = __ldg(yp + base);
    float4 v1 = __ldg(yp + base + SS);
    float4 v2 = __ldg(yp + base + 2 * SS);
    float4 v3 = __ldg(yp + base + 3 * SS);
    float4 m;
    m.x = c0 * v0.x + c1 * v1.x + c2 * v2.x + c3 * v3.x;
    m.y = c0 * v0.y + c1 * v1.y + c2 * v2.y + c3 * v3.y;
    m.z = c0 * v0.z + c1 * v1.z + c2 * v2.z + c3 * v3.z;
    m.w = c0 * v0.w + c1 * v1.w + c2 * v2.w + c3 * v3.w;
    redAdd4(out + (long)d * HH + lane * 4, m);
}

// ---------------- layer 2 transform, F=16: grid.y = 5 (4 bases -> Z, slot 4 -> out+bias) ----------------
__global__ void __launch_bounds__(128) transform16(
    const float* __restrict__ X, const float* __restrict__ bases2,
    const float* __restrict__ loop2, const float* __restrict__ bias2,
    float* __restrict__ Z, float* __restrict__ out) {
    __shared__ float ws[128 * 16];
    __shared__ float xs[64][129];
    const int y = blockIdx.y;
    const float* W = (y < 4) ? (bases2 + y * 2048) : loop2;
    float* O = (y < 4) ? (Z + (long)y * NN * CC) : out;
    const int t = threadIdx.x;
    const int col = t & 15, rg = t >> 4;
    const int row0 = blockIdx.x * 64;
    for (int i = t; i < 128 * 16; i += 128) ws[i] = __ldg(&W[i]);
#pragma unroll 4
    for (int i = 0; i < 64; i++) {
        int rr = row0 + i;
        float v = (rr < NN) ? __ldg(&X[(long)rr * 128 + t]) : 0.f;
        xs[i][t] = fmaxf(v, 0.f);   // relu(x1) fused
    }
    __syncthreads();
    const float bv = (y == 4) ? __ldg(&bias2[col]) : 0.f;
    for (int p = 0; p < 8; p++) {
        int rl = p * 8 + rg;
        float a = 0.f;
#pragma unroll 16
        for (int d = 0; d < 128; d++) a = fmaf(xs[rl][d], ws[d * 16 + col], a);
        int rr = row0 + rl;
        if (rr < NN) O[(long)rr * 16 + col] = a + bv;
    }
}

// ---------------- layer 2 scatter: 4 lanes per edge, gather 4 basis rows of Z ----------------
__global__ void __launch_bounds__(256) scatter2_k(
    const int* __restrict__ src, const int* __restrict__ dst, const int* __restrict__ rel,
    const float* __restrict__ norm, const float* __restrict__ wcomp2,
    const float* __restrict__ Z, float* __restrict__ out) {
    int tid = blockIdx.x * 256 + threadIdx.x;
    int e = tid >> 2;
    if (e >= EE) return;
    int q = tid & 3;
    int s = __ldg(&src[e]);
    int d = __ldg(&dst[e]);
    int rr = __ldg(&rel[e]);
    float nm = __ldg(&norm[e]);
    float c0 = nm * __ldg(&wcomp2[rr * 4 + 0]);
    float c1 = nm * __ldg(&wcomp2[rr * 4 + 1]);
    float c2 = nm * __ldg(&wcomp2[rr * 4 + 2]);
    float c3 = nm * __ldg(&wcomp2[rr * 4 + 3]);
    const float4* zp = (const float4*)Z;
    const long SS = (long)NN * 4;
    long base = (long)s * 4 + q;
    float4 v0 = __ldg(zp + base);
    float4 v1 = __ldg(zp + base + SS);
    float4 v2 = __ldg(zp + base + 2 * SS);
    float4 v3 = __ldg(zp + base + 3 * SS);
    float4 m;
    m.x = c0 * v0.x + c1 * v1.x + c2 * v2.x + c3 * v3.x;
    m.y = c0 * v0.y + c1 * v1.y + c2 * v2.y + c3 * v3.y;
    m.z = c0 * v0.z + c1 * v1.z + c2 * v2.z + c3 * v3.z;
    m.w = c0 * v0.w + c1 * v1.w + c2 * v2.w + c3 * v3.w;
    redAdd4(out + (long)d * CC + q * 4, m);
}

// ---------------- launch ----------------
extern "C" void kernel_launch(void* const* d_in, const int* in_sizes, int n_in,
                              void* d_out, int out_size) {
    const int*   src    = (const int*)d_in[0];
    const int*   dst    = (const int*)d_in[1];
    const int*   h      = (const int*)d_in[2];
    const int*   rtab   = (const int*)d_in[3];
    const float* norm   = (const float*)d_in[4];
    const float* bases0 = (const float*)d_in[5];
    const float* wcomp0 = (const float*)d_in[6];
    const float* loop0  = (const float*)d_in[7];
    const float* bias0  = (const float*)d_in[8];
    const float* bases1 = (const float*)d_in[9];
    const float* wcomp1 = (const float*)d_in[10];
    const float* loop1  = (const float*)d_in[11];
    const float* bias1  = (const float*)d_in[12];
    const float* bases2 = (const float*)d_in[13];
    const float* wcomp2 = (const float*)d_in[14];
    const float* loop2  = (const float*)d_in[15];
    const float* bias2  = (const float*)d_in[16];
    float* out = (float*)d_out;

    float *p_x0, *p_x1, *p_y1, *p_z2;
    __nv_bfloat16 *p_whi, *p_wlo;
    cudaGetSymbolAddress((void**)&p_x0, g_x0);
    cudaGetSymbolAddress((void**)&p_x1, g_x1);
    cudaGetSymbolAddress((void**)&p_y1, g_y1);
    cudaGetSymbolAddress((void**)&p_z2, g_z2);
    cudaGetSymbolAddress((void**)&p_whi, g_w1thi);
    cudaGetSymbolAddress((void**)&p_wlo, g_w1tlo);

    static int attr_done = 0;
    if (!attr_done) {
        cudaFuncSetAttribute(mma_t128, cudaFuncAttributeMaxDynamicSharedMemorySize, SMEM_MMA);
        attr_done = 1;
    }

    const int nh_blocks = (NN * HH + 255) / 256;
    const int edge_warp = (EE * 32 + 255) / 256;
    const int row_t128  = (NN + 127) / 128;   // 391
    const int row_t64   = (NN + 63) / 64;     // 782

    // weight prep (bf16 hi/lo transposed images for HMMA)
    prep_w1t<<<(5 * 16384 + 255) / 256, 256>>>(bases1, loop1, p_whi, p_wlo);

    // ---- layer 0 ----
    init0_k<<<nh_blocks, 256>>>(h, loop0, bias0, p_x0);
    scatter0_k<<<edge_warp, 256>>>(src, dst, h, rtab, norm, bases0, wcomp0, p_x0);

    // ---- layer 1: basis products via HMMA, then basis-gather scatter ----
    mma_t128<<<dim3(row_t128, 5), 256, SMEM_MMA>>>(p_x0, p_whi, p_wlo, p_y1, p_x1, bias1);
    scatter1_k<<<edge_warp, 256>>>(src, dst, rtab, norm, wcomp1, p_y1, p_x1);

    // ---- layer 2 ----
    transform16<<<dim3(row_t64, 5), 128>>>(p_x1, bases2, loop2, bias2, p_z2, out);
    scatter2_k<<<(EE * 4 + 255) / 256, 256>>>(src, dst, rtab, norm, wcomp2, p_z2, out);
}